// round 13
// baseline (speedup 1.0000x reference)
#include <cuda_runtime.h>
#include <cuda_fp16.h>
#include <cstdint>

#define EMBED   2048
#define NHEADS  16
#define HDIM    128
#define SEQ     2048
#define BATCH   2
#define QKVN    (3*EMBED)      /* 6144 */
#define MROWS   (BATCH*SEQ)    /* 4096 */

// Scratch (static device globals — allocation-free).
__device__ __align__(16) __half g_q16[(size_t)MROWS * EMBED];   // Q fp16 perm16, scaled*log2e
__device__ __align__(16) __half g_k16[(size_t)MROWS * EMBED];   // K fp16 perm16
__device__ __align__(16) __half g_v16[(size_t)MROWS * EMBED];   // V [bh,d,2048keys] perm16
__device__ __align__(16) __half g_attnH[(size_t)MROWS * EMBED]; // attn out fp16 perm16
__device__ __align__(16) __half g_Bt[(size_t)QKVN * EMBED];     // weights [N,K] fp16 perm16
__device__ __align__(16) __half g_xH[(size_t)MROWS * EMBED];    // x fp16 perm16

#define ATT_SCALE 0.08838834764831845f           /* 1/sqrt(128) */
#define LOG2E     1.4426950408889634f
#define QSCALE    (ATT_SCALE * LOG2E)            /* folded: softmax in exp2 domain */

__device__ __forceinline__ void mma_f16(float* c,
                                        uint32_t a0, uint32_t a1, uint32_t a2, uint32_t a3,
                                        uint32_t b0, uint32_t b1) {
    asm volatile(
        "mma.sync.aligned.m16n8k16.row.col.f32.f16.f16.f32 "
        "{%0,%1,%2,%3}, {%4,%5,%6,%7}, {%8,%9}, {%0,%1,%2,%3};"
        : "+f"(c[0]), "+f"(c[1]), "+f"(c[2]), "+f"(c[3])
        : "r"(a0), "r"(a1), "r"(a2), "r"(a3), "r"(b0), "r"(b1));
}
__device__ __forceinline__ uint32_t h2u(half2 h) {
    return *reinterpret_cast<uint32_t*>(&h);
}
__device__ __forceinline__ uint32_t smem_u32(const void* p) {
    uint32_t a;
    asm("{ .reg .u64 t; cvta.to.shared.u64 t, %1; cvt.u32.u64 %0, t; }"
        : "=r"(a) : "l"(p));
    return a;
}
__device__ __forceinline__ void cp16(uint32_t dst, const void* src) {
    asm volatile("cp.async.ca.shared.global [%0], [%1], 16;"
                 :: "r"(dst), "l"(src) : "memory");
}
#define CP_COMMIT() asm volatile("cp.async.commit_group;" ::: "memory")
#define CP_WAIT0()  asm volatile("cp.async.wait_group 0;"  ::: "memory")
#define CP_WAIT1()  asm volatile("cp.async.wait_group 1;"  ::: "memory")

// fp16 m16n8k16 fragment permutation within a 32-half K-block:
//   slot = ((k&7)>>1)*8 + ((k>>4)&1)*4 + ((k>>3)&1)*2 + (k&1)
__device__ __forceinline__ int perm16(int k) {
    return (((k & 7) >> 1) << 3) + (((k >> 4) & 1) << 2) + (((k >> 3) & 1) << 1) + (k & 1);
}

// ---------------------------------------------------------------------------
// x fp32 [M,2048] -> fp16 perm16 layout.
// ---------------------------------------------------------------------------
__global__ void permute_h16(const float* __restrict__ in, __half* __restrict__ out,
                            int total4)
{
    for (int idx = blockIdx.x * blockDim.x + threadIdx.x; idx < total4;
         idx += gridDim.x * blockDim.x) {
        float4 v = *(const float4*)(in + 4 * (size_t)idx);
        int row = idx >> 9;
        int c4  = idx & 511;
        int w   = 4 * (c4 & 7);
        __half* dst = out + (size_t)row * EMBED + ((c4 >> 3) << 5);
        *(half2*)(dst + perm16(w))     = __floats2half2_rn(v.x, v.y);
        *(half2*)(dst + perm16(w + 2)) = __floats2half2_rn(v.z, v.w);
    }
}

// ---------------------------------------------------------------------------
// Weight transpose + fp16 + perm16:  W[K,N] fp32 -> Wt[N,K] fp16 fragment layout
// ---------------------------------------------------------------------------
__global__ void transpose_h16(const float* __restrict__ W, __half* __restrict__ Wt,
                              int K, int N)
{
    __shared__ float t[32][33];
    const int kb = blockIdx.y * 32, nb = blockIdx.x * 32;
    const int x = threadIdx.x, y = threadIdx.y;  // (32, 8)
    #pragma unroll
    for (int i = 0; i < 32; i += 8)
        t[y + i][x] = W[(size_t)(kb + y + i) * N + nb + x];
    __syncthreads();
    #pragma unroll
    for (int i = 0; i < 32; i += 8)
        Wt[(size_t)(nb + y + i) * K + kb + perm16(x)] = __float2half_rn(t[x][y + i]);
}

// ---------------------------------------------------------------------------
// FP16 mma.sync (m16n8k16) GEMM, cp.async 3-stage pipeline, 2 CTAs/SM.
// (unchanged from Round 12 — at the mma.sync issue ceiling)
// ---------------------------------------------------------------------------
#define STAGE_B 16384
#define NSTAGE 3
#define GEMM_SMEM (NSTAGE * STAGE_B)     /* 49152 -> 2 CTAs/SM */

__global__ __launch_bounds__(256, 2)
void gemm_mma(const __half* __restrict__ Ap, const __half* __restrict__ Bp,
              const float* __restrict__ bias, float* __restrict__ C,
              int M, int N, int K, int mode)
{
    extern __shared__ char smc[];
    const uint32_t smb = smem_u32(smc);

    const int tid  = threadIdx.x;
    const int lane = tid & 31;
    const int wid  = tid >> 5;
    const int wm   = wid & 3;
    const int wn   = wid >> 2;
    const int m0   = blockIdx.y * 128;
    const int n0   = blockIdx.x * 128;
    const int gp   = lane >> 2;
    const int cc   = lane & 3;

    auto fill = [&](int s, int st) {
        const int k0 = s << 5;
        uint32_t dA = smb + (uint32_t)(st * STAGE_B);
        uint32_t dB = dA + 8192;
        const __half* As = Ap + (size_t)m0 * K + k0;
        const __half* Bs = Bp + (size_t)n0 * K + k0;
        #pragma unroll
        for (int t = 0; t < 2; t++) {
            int idx = tid + 256 * t;
            int row = idx >> 2, ch = idx & 3;
            uint32_t off = (uint32_t)(row * 64 + ((ch ^ (row & 3)) << 4));
            cp16(dA + off, As + (size_t)row * K + ch * 8);
            cp16(dB + off, Bs + (size_t)row * K + ch * 8);
        }
    };

    float acc[2][8][4];
    #pragma unroll
    for (int ma = 0; ma < 2; ma++)
        #pragma unroll
        for (int nn = 0; nn < 8; nn++)
            #pragma unroll
            for (int q = 0; q < 4; q++) acc[ma][nn][q] = 0.f;

    fill(0, 0); CP_COMMIT();
    fill(1, 1); CP_COMMIT();

    const int chsw = cc ^ (gp & 3);
    const int NST = K >> 5;
    int st = 0;
    for (int s = 0; s < NST; s++) {
        CP_WAIT1();
        __syncthreads();

        const char* a = smc + st * STAGE_B;
        const char* b = a + 8192;

        uint4 av[4];
        #pragma unroll
        for (int r = 0; r < 4; r++) {
            int row = wm * 32 + gp + 8 * r;
            av[r] = *(const uint4*)(a + row * 64 + (chsw << 4));
        }
        #pragma unroll
        for (int nh = 0; nh < 2; nh++) {
            uint4 bv[4];
            #pragma unroll
            for (int j = 0; j < 4; j++) {
                int row = wn * 64 + 8 * (4 * nh + j) + gp;
                bv[j] = *(const uint4*)(b + row * 64 + (chsw << 4));
            }
            #pragma unroll
            for (int ma = 0; ma < 2; ma++) {
                #pragma unroll
                for (int j = 0; j < 4; j++)
                    mma_f16(acc[ma][4 * nh + j], av[2 * ma].x, av[2 * ma + 1].x,
                            av[2 * ma].y, av[2 * ma + 1].y, bv[j].x, bv[j].y);
                #pragma unroll
                for (int j = 0; j < 4; j++)
                    mma_f16(acc[ma][4 * nh + j], av[2 * ma].z, av[2 * ma + 1].z,
                            av[2 * ma].w, av[2 * ma + 1].w, bv[j].z, bv[j].w);
            }
        }
        if (s + 2 < NST) {
            int nb = st + 2; if (nb >= 3) nb -= 3;
            fill(s + 2, nb);
        }
        CP_COMMIT();
        if (++st == 3) st = 0;
    }

    if (mode == 0) {
        #pragma unroll
        for (int ma = 0; ma < 2; ma++) {
            int rbase = m0 + wm * 32 + ma * 16 + gp;
            #pragma unroll
            for (int half = 0; half < 2; half++) {
                int r = rbase + 8 * half;
                #pragma unroll
                for (int nn = 0; nn < 8; nn++) {
                    int col = n0 + wn * 64 + 8 * nn + 2 * cc;
                    float2 bb = *(const float2*)(bias + col);
                    float2 o;
                    o.x = acc[ma][nn][2 * half + 0] + bb.x;
                    o.y = acc[ma][nn][2 * half + 1] + bb.y;
                    *(float2*)(C + (size_t)r * N + col) = o;
                }
            }
        }
    } else {
        const int region = n0 >> 11;   // 0=Q, 1=K, 2=V
        #pragma unroll
        for (int ma = 0; ma < 2; ma++) {
            #pragma unroll
            for (int half = 0; half < 2; half++) {
                int r  = m0 + wm * 32 + ma * 16 + gp + 8 * half;
                int bb = r >> 11;
                int s  = r & 2047;
                #pragma unroll
                for (int nn = 0; nn < 8; nn++) {
                    int col = n0 + wn * 64 + 8 * nn + 2 * cc;   // even
                    float v0 = acc[ma][nn][2 * half + 0] + bias[col];
                    float v1 = acc[ma][nn][2 * half + 1] + bias[col + 1];
                    int hd = col & 2047;
                    int h  = hd >> 7;
                    int w  = hd & 127;                          // even
                    int bh = bb * 16 + h;
                    if (region == 0) {
                        __half* dst = g_q16 + ((size_t)bh * SEQ + s) * HDIM +
                                      ((w >> 5) << 5) + perm16(w & 31);
                        *(half2*)dst = __floats2half2_rn(v0 * QSCALE, v1 * QSCALE);
                    } else if (region == 1) {
                        __half* dst = g_k16 + ((size_t)bh * SEQ + s) * HDIM +
                                      ((w >> 5) << 5) + perm16(w & 31);
                        *(half2*)dst = __floats2half2_rn(v0, v1);
                    } else {
                        size_t koff = ((size_t)(s >> 5) << 5) + perm16(s & 31);
                        g_v16[((size_t)bh * HDIM + w) * SEQ + koff] = __float2half_rn(v0);
                        g_v16[((size_t)bh * HDIM + w + 1) * SEQ + koff] = __float2half_rn(v1);
                    }
                }
            }
        }
    }
}

// ---------------------------------------------------------------------------
// Flash-attention, all-fp16 mma, exp2 softmax, SOFTWARE-PIPELINED across
// tiles: S(kt+1) is issued at the END of body(kt); softmax(kt) runs at the
// TOP of body(kt) on accumulators issued a full tile earlier (chains drained
// behind PV + barriers + fills). Final-tile skip for fully-masked warps.
// ---------------------------------------------------------------------------
#define Q16_B 32768                    /* 128 rows x 4 planes x 64B */
#define K16_B 16384                    /* 64 x 4 x 64 */
#define V16_B 16384                    /* 128 x 2 x 64 */
#define ATTN_SMEM (Q16_B + 2*K16_B + 2*V16_B)   /* 98304 */

__global__ __launch_bounds__(256, 2)
void attn_mma()
{
    extern __shared__ char smc[];
    const uint32_t smb = smem_u32(smc);
    const uint32_t uQ = smb;
    const uint32_t uK = smb + Q16_B;
    const uint32_t uV = smb + Q16_B + 2 * K16_B;

    const int tid  = threadIdx.x;
    const int lane = tid & 31;
    const int wid  = tid >> 5;
    const int gp   = lane >> 2;
    const int cc   = lane & 3;
    const int qt   = (int)gridDim.x - 1 - (int)blockIdx.x;
    const int bh   = blockIdx.y;
    const size_t qbase = (size_t)bh * SEQ;

    auto fillQ = [&]() {
        #pragma unroll
        for (int t = 0; t < 8; t++) {
            int idx = tid + 256 * t;
            int r = idx >> 4, b = (idx >> 2) & 3, ch = idx & 3;
            cp16(uQ + (uint32_t)(b * 8192 + r * 64 + ((ch ^ (r & 3)) << 4)),
                 g_q16 + (qbase + qt * 128 + r) * HDIM + b * 32 + ch * 8);
        }
    };
    auto fillK = [&](int kt, int buf) {
        uint32_t base = uK + (uint32_t)(buf * K16_B);
        #pragma unroll
        for (int t = 0; t < 4; t++) {
            int idx = tid + 256 * t;
            int r = idx >> 4, b = (idx >> 2) & 3, ch = idx & 3;
            cp16(base + (uint32_t)(b * 4096 + r * 64 + ((ch ^ (r & 3)) << 4)),
                 g_k16 + (qbase + kt * 64 + r) * HDIM + b * 32 + ch * 8);
        }
    };
    auto fillV = [&](int kt, int buf) {
        uint32_t base = uV + (uint32_t)(buf * V16_B);
        #pragma unroll
        for (int t = 0; t < 4; t++) {
            int idx = tid + 256 * t;
            int d = idx >> 3, b = (idx >> 2) & 1, ch = idx & 3;
            cp16(base + (uint32_t)(b * 8192 + d * 64 + ((ch ^ (d & 3)) << 4)),
                 g_v16 + ((size_t)bh * HDIM + d) * SEQ + kt * 64 + b * 32 + ch * 8);
        }
    };

    const int qrow = wid * 16 + gp;
    const int chA  = (cc ^ (qrow & 3)) << 4;
    const int chB  = (cc ^ (gp & 3)) << 4;

    float sacc[8][4];
    auto computeS = [&](int buf) {
        #pragma unroll
        for (int nn = 0; nn < 8; nn++)
            #pragma unroll
            for (int q = 0; q < 4; q++) sacc[nn][q] = 0.f;
        #pragma unroll
        for (int b = 0; b < 4; b++) {
            const char* qp = smc + b * 8192;
            const char* kp = smc + Q16_B + buf * K16_B + b * 4096;
            uint4 avA = *(const uint4*)(qp + qrow * 64 + chA);
            uint4 avB = *(const uint4*)(qp + (qrow + 8) * 64 + chA);
            #pragma unroll
            for (int nn = 0; nn < 8; nn++) {
                uint4 bk = *(const uint4*)(kp + (8 * nn + gp) * 64 + chB);
                mma_f16(sacc[nn], avA.x, avB.x, avA.y, avB.y, bk.x, bk.y);
                mma_f16(sacc[nn], avA.z, avB.z, avA.w, avB.w, bk.z, bk.w);
            }
        }
    };

    float m[2] = {-1e30f, -1e30f}, l[2] = {0.f, 0.f};
    float oacc[16][4];
    #pragma unroll
    for (int nd = 0; nd < 16; nd++)
        #pragma unroll
        for (int q = 0; q < 4; q++) oacc[nd][q] = 0.f;

    const int nkt = 2 * qt + 2;          // >= 2 always

    // ---- prologue: fill tiles 0 and 1; compute S(0) ----
    fillQ(); fillK(0, 0); fillV(0, 0); CP_COMMIT();
    fillK(1, 1); fillV(1, 1); CP_COMMIT();
    CP_WAIT1();                           // group(Q,K0,V0) done; (K1,V1) may fly
    __syncthreads();
    computeS(0);

    for (int kt = 0; kt < nkt; kt++) {
        const int buf = kt & 1;
        CP_WAIT0();                       // K(kt+1), V(kt+1) landed
        __syncthreads();

        // final tile is fully masked for warps 0-3 (their q-rows < tile keys)
        const bool act = !((kt == nkt - 1) && wid < 4);

        uint32_t ah[4][4];
        if (act) {
            // ---- causal mask (straddling tiles only) ----
            if (kt >= 2 * qt) {
                #pragma unroll
                for (int hq = 0; hq < 2; hq++) {
                    int qg = qt * 128 + qrow + 8 * hq;
                    #pragma unroll
                    for (int nn = 0; nn < 8; nn++) {
                        int k0 = kt * 64 + 8 * nn + 2 * cc;
                        if (k0 > qg)     sacc[nn][2 * hq]     = -1e30f;
                        if (k0 + 1 > qg) sacc[nn][2 * hq + 1] = -1e30f;
                    }
                }
            }
            // ---- online softmax (exp2 domain); S chains drained a tile ago ----
            #pragma unroll
            for (int hq = 0; hq < 2; hq++) {
                float mx = -1e30f;
                #pragma unroll
                for (int nn = 0; nn < 8; nn++)
                    mx = fmaxf(mx, fmaxf(sacc[nn][2 * hq], sacc[nn][2 * hq + 1]));
                mx = fmaxf(mx, __shfl_xor_sync(0xffffffffu, mx, 1));
                mx = fmaxf(mx, __shfl_xor_sync(0xffffffffu, mx, 2));
                float mnew = fmaxf(m[hq], mx);
                float corr = exp2f(m[hq] - mnew);
                m[hq] = mnew;
                float rs = 0.f;
                #pragma unroll
                for (int nn = 0; nn < 8; nn++) {
                    float p0 = exp2f(sacc[nn][2 * hq]     - mnew);
                    float p1 = exp2f(sacc[nn][2 * hq + 1] - mnew);
                    rs += p0 + p1;
                    ah[nn >> 1][((nn & 1) << 1) | hq] = h2u(__floats2half2_rn(p0, p1));
                }
                rs += __shfl_xor_sync(0xffffffffu, rs, 1);
                rs += __shfl_xor_sync(0xffffffffu, rs, 2);
                l[hq] = l[hq] * corr + rs;
                #pragma unroll
                for (int nd = 0; nd < 16; nd++) {
                    oacc[nd][2 * hq]     *= corr;
                    oacc[nd][2 * hq + 1] *= corr;
                }
            }
            // ---- O += P V ----
            #pragma unroll
            for (int pl = 0; pl < 2; pl++) {
                const char* vp = smc + Q16_B + 2 * K16_B + buf * V16_B + pl * 8192;
                #pragma unroll
                for (int nd = 0; nd < 16; nd++) {
                    uint4 bv = *(const uint4*)(vp + (8 * nd + gp) * 64 + chB);
                    mma_f16(oacc[nd], ah[2 * pl][0], ah[2 * pl][1],
                            ah[2 * pl][2], ah[2 * pl][3], bv.x, bv.y);
                    mma_f16(oacc[nd], ah[2 * pl + 1][0], ah[2 * pl + 1][1],
                            ah[2 * pl + 1][2], ah[2 * pl + 1][3], bv.z, bv.w);
                }
            }
        }

        // ---- issue S(kt+1) now; its chains drain behind barrier + fills ----
        if (kt + 1 < nkt && !((kt + 1 == nkt - 1) && wid < 4))
            computeS(1 - buf);

        __syncthreads();                  // buf (K&V) fully consumed by all warps
        if (kt + 2 < nkt) {
            fillK(kt + 2, buf);           // (kt+2)&1 == buf
            fillV(kt + 2, buf);
            CP_COMMIT();
        }
    }

    // ---- normalize + store (fp16 perm16 for out-proj GEMM) ----
    const int b = bh >> 4, h = bh & 15;
    #pragma unroll
    for (int hq = 0; hq < 2; hq++) {
        float inv = 1.0f / l[hq];
        size_t row = (size_t)b * SEQ + qt * 128 + wid * 16 + gp + 8 * hq;
        __half* dst = g_attnH + row * EMBED;
        #pragma unroll
        for (int nd = 0; nd < 16; nd++) {
            float o0 = oacc[nd][2 * hq]     * inv;
            float o1 = oacc[nd][2 * hq + 1] * inv;
            int j   = 8 * nd + 2 * cc;
            int blk = (h * HDIM + j) >> 5;
            *(half2*)(dst + blk * 32 + perm16(j & 31)) = __floats2half2_rn(o0, o1);
        }
    }
}

// ---------------------------------------------------------------------------
extern "C" void kernel_launch(void* const* d_in, const int* in_sizes, int n_in,
                              void* d_out, int out_size)
{
    const float* x    = (const float*)d_in[0];
    const float* Wqkv = (const float*)d_in[1];
    const float* bqkv = (const float*)d_in[2];
    const float* Wout = (const float*)d_in[3];
    const float* bout = (const float*)d_in[4];
    float* out = (float*)d_out;

    __half* attp = nullptr;
    __half* btp  = nullptr;
    __half* xpp  = nullptr;
    cudaGetSymbolAddress((void**)&attp, g_attnH);
    cudaGetSymbolAddress((void**)&btp,  g_Bt);
    cudaGetSymbolAddress((void**)&xpp,  g_xH);

    cudaFuncSetAttribute(attn_mma,
                         cudaFuncAttributeMaxDynamicSharedMemorySize, ATTN_SMEM);
    cudaFuncSetAttribute(gemm_mma,
                         cudaFuncAttributeMaxDynamicSharedMemorySize, GEMM_SMEM);

    // 1) x -> fp16 perm16
    permute_h16<<<2048, 256>>>(x, xpp, MROWS * EMBED / 4);
    // 2) W_qkv -> [N,K] fp16 perm16
    transpose_h16<<<dim3(QKVN / 32, EMBED / 32), dim3(32, 8)>>>(Wqkv, btp, EMBED, QKVN);
    // 3) QKV projection (fp16 mma), fused epilogue -> g_q16 / g_k16 / g_v16
    gemm_mma<<<dim3(QKVN / 128, MROWS / 128), 256, GEMM_SMEM>>>(
        xpp, btp, bqkv, nullptr, MROWS, QKVN, EMBED, 1);
    // 4) causal attention (fp16 mma, pipelined softmax, 2 CTAs/SM)
    attn_mma<<<dim3(SEQ / 128, BATCH * NHEADS), 256, ATTN_SMEM>>>();
    // 5) W_out -> [N,K] fp16 perm16
    transpose_h16<<<dim3(EMBED / 32, EMBED / 32), dim3(32, 8)>>>(Wout, btp, EMBED, EMBED);
    // 6) output projection (fp16 mma)
    gemm_mma<<<dim3(EMBED / 128, MROWS / 128), 256, GEMM_SMEM>>>(
        attp, btp, bout, out, MROWS, EMBED, EMBED, 0);
}

// round 14
// speedup vs baseline: 1.0082x; 1.0082x over previous
#include <cuda_runtime.h>
#include <cuda_fp16.h>
#include <cstdint>

#define EMBED   2048
#define NHEADS  16
#define HDIM    128
#define SEQ     2048
#define BATCH   2
#define QKVN    (3*EMBED)      /* 6144 */
#define MROWS   (BATCH*SEQ)    /* 4096 */

// Scratch (static device globals — allocation-free).
__device__ __align__(16) __half g_q16[(size_t)MROWS * EMBED];   // Q fp16 perm16, scaled*log2e
__device__ __align__(16) __half g_k16[(size_t)MROWS * EMBED];   // K fp16 perm16
__device__ __align__(16) __half g_v16[(size_t)MROWS * EMBED];   // V [bh,d,2048keys] perm16
__device__ __align__(16) __half g_attnH[(size_t)MROWS * EMBED]; // attn out fp16 perm16
__device__ __align__(16) __half g_Bt[(size_t)QKVN * EMBED];     // weights [N,K] fp16 perm16
__device__ __align__(16) __half g_xH[(size_t)MROWS * EMBED];    // x fp16 perm16

#define ATT_SCALE 0.08838834764831845f           /* 1/sqrt(128) */
#define LOG2E     1.4426950408889634f
#define QSCALE    (ATT_SCALE * LOG2E)            /* folded: softmax in exp2 domain */

__device__ __forceinline__ void mma_f16(float* c,
                                        uint32_t a0, uint32_t a1, uint32_t a2, uint32_t a3,
                                        uint32_t b0, uint32_t b1) {
    asm volatile(
        "mma.sync.aligned.m16n8k16.row.col.f32.f16.f16.f32 "
        "{%0,%1,%2,%3}, {%4,%5,%6,%7}, {%8,%9}, {%0,%1,%2,%3};"
        : "+f"(c[0]), "+f"(c[1]), "+f"(c[2]), "+f"(c[3])
        : "r"(a0), "r"(a1), "r"(a2), "r"(a3), "r"(b0), "r"(b1));
}
__device__ __forceinline__ uint32_t h2u(half2 h) {
    return *reinterpret_cast<uint32_t*>(&h);
}
__device__ __forceinline__ uint32_t smem_u32(const void* p) {
    uint32_t a;
    asm("{ .reg .u64 t; cvta.to.shared.u64 t, %1; cvt.u32.u64 %0, t; }"
        : "=r"(a) : "l"(p));
    return a;
}
__device__ __forceinline__ void cp16(uint32_t dst, const void* src) {
    asm volatile("cp.async.ca.shared.global [%0], [%1], 16;"
                 :: "r"(dst), "l"(src) : "memory");
}
#define CP_COMMIT() asm volatile("cp.async.commit_group;" ::: "memory")
#define CP_WAIT0()  asm volatile("cp.async.wait_group 0;"  ::: "memory")
#define CP_WAIT1()  asm volatile("cp.async.wait_group 1;"  ::: "memory")

// fp16 m16n8k16 fragment permutation within a 32-half K-block:
//   slot = ((k&7)>>1)*8 + ((k>>4)&1)*4 + ((k>>3)&1)*2 + (k&1)
__device__ __forceinline__ int perm16(int k) {
    return (((k & 7) >> 1) << 3) + (((k >> 4) & 1) << 2) + (((k >> 3) & 1) << 1) + (k & 1);
}

// ---------------------------------------------------------------------------
// x fp32 [M,2048] -> fp16 perm16 layout.
// ---------------------------------------------------------------------------
__global__ void permute_h16(const float* __restrict__ in, __half* __restrict__ out,
                            int total4)
{
    for (int idx = blockIdx.x * blockDim.x + threadIdx.x; idx < total4;
         idx += gridDim.x * blockDim.x) {
        float4 v = *(const float4*)(in + 4 * (size_t)idx);
        int row = idx >> 9;
        int c4  = idx & 511;
        int w   = 4 * (c4 & 7);
        __half* dst = out + (size_t)row * EMBED + ((c4 >> 3) << 5);
        *(half2*)(dst + perm16(w))     = __floats2half2_rn(v.x, v.y);
        *(half2*)(dst + perm16(w + 2)) = __floats2half2_rn(v.z, v.w);
    }
}

// ---------------------------------------------------------------------------
// Weight transpose + fp16 + perm16:  W[K,N] fp32 -> Wt[N,K] fp16 fragment layout
// ---------------------------------------------------------------------------
__global__ void transpose_h16(const float* __restrict__ W, __half* __restrict__ Wt,
                              int K, int N)
{
    __shared__ float t[32][33];
    const int kb = blockIdx.y * 32, nb = blockIdx.x * 32;
    const int x = threadIdx.x, y = threadIdx.y;  // (32, 8)
    #pragma unroll
    for (int i = 0; i < 32; i += 8)
        t[y + i][x] = W[(size_t)(kb + y + i) * N + nb + x];
    __syncthreads();
    #pragma unroll
    for (int i = 0; i < 32; i += 8)
        Wt[(size_t)(nb + y + i) * K + kb + perm16(x)] = __float2half_rn(t[x][y + i]);
}

// ---------------------------------------------------------------------------
// FP16 mma.sync (m16n8k16) GEMM, cp.async 3-stage pipeline, 2 CTAs/SM.
// (unchanged — at the mma.sync issue ceiling)
// ---------------------------------------------------------------------------
#define STAGE_B 16384
#define NSTAGE 3
#define GEMM_SMEM (NSTAGE * STAGE_B)     /* 49152 -> 2 CTAs/SM */

__global__ __launch_bounds__(256, 2)
void gemm_mma(const __half* __restrict__ Ap, const __half* __restrict__ Bp,
              const float* __restrict__ bias, float* __restrict__ C,
              int M, int N, int K, int mode)
{
    extern __shared__ char smc[];
    const uint32_t smb = smem_u32(smc);

    const int tid  = threadIdx.x;
    const int lane = tid & 31;
    const int wid  = tid >> 5;
    const int wm   = wid & 3;
    const int wn   = wid >> 2;
    const int m0   = blockIdx.y * 128;
    const int n0   = blockIdx.x * 128;
    const int gp   = lane >> 2;
    const int cc   = lane & 3;

    auto fill = [&](int s, int st) {
        const int k0 = s << 5;
        uint32_t dA = smb + (uint32_t)(st * STAGE_B);
        uint32_t dB = dA + 8192;
        const __half* As = Ap + (size_t)m0 * K + k0;
        const __half* Bs = Bp + (size_t)n0 * K + k0;
        #pragma unroll
        for (int t = 0; t < 2; t++) {
            int idx = tid + 256 * t;
            int row = idx >> 2, ch = idx & 3;
            uint32_t off = (uint32_t)(row * 64 + ((ch ^ (row & 3)) << 4));
            cp16(dA + off, As + (size_t)row * K + ch * 8);
            cp16(dB + off, Bs + (size_t)row * K + ch * 8);
        }
    };

    float acc[2][8][4];
    #pragma unroll
    for (int ma = 0; ma < 2; ma++)
        #pragma unroll
        for (int nn = 0; nn < 8; nn++)
            #pragma unroll
            for (int q = 0; q < 4; q++) acc[ma][nn][q] = 0.f;

    fill(0, 0); CP_COMMIT();
    fill(1, 1); CP_COMMIT();

    const int chsw = cc ^ (gp & 3);
    const int NST = K >> 5;
    int st = 0;
    for (int s = 0; s < NST; s++) {
        CP_WAIT1();
        __syncthreads();

        const char* a = smc + st * STAGE_B;
        const char* b = a + 8192;

        uint4 av[4];
        #pragma unroll
        for (int r = 0; r < 4; r++) {
            int row = wm * 32 + gp + 8 * r;
            av[r] = *(const uint4*)(a + row * 64 + (chsw << 4));
        }
        #pragma unroll
        for (int nh = 0; nh < 2; nh++) {
            uint4 bv[4];
            #pragma unroll
            for (int j = 0; j < 4; j++) {
                int row = wn * 64 + 8 * (4 * nh + j) + gp;
                bv[j] = *(const uint4*)(b + row * 64 + (chsw << 4));
            }
            #pragma unroll
            for (int ma = 0; ma < 2; ma++) {
                #pragma unroll
                for (int j = 0; j < 4; j++)
                    mma_f16(acc[ma][4 * nh + j], av[2 * ma].x, av[2 * ma + 1].x,
                            av[2 * ma].y, av[2 * ma + 1].y, bv[j].x, bv[j].y);
                #pragma unroll
                for (int j = 0; j < 4; j++)
                    mma_f16(acc[ma][4 * nh + j], av[2 * ma].z, av[2 * ma + 1].z,
                            av[2 * ma].w, av[2 * ma + 1].w, bv[j].z, bv[j].w);
            }
        }
        if (s + 2 < NST) {
            int nb = st + 2; if (nb >= 3) nb -= 3;
            fill(s + 2, nb);
        }
        CP_COMMIT();
        if (++st == 3) st = 0;
    }

    if (mode == 0) {
        #pragma unroll
        for (int ma = 0; ma < 2; ma++) {
            int rbase = m0 + wm * 32 + ma * 16 + gp;
            #pragma unroll
            for (int half = 0; half < 2; half++) {
                int r = rbase + 8 * half;
                #pragma unroll
                for (int nn = 0; nn < 8; nn++) {
                    int col = n0 + wn * 64 + 8 * nn + 2 * cc;
                    float2 bb = *(const float2*)(bias + col);
                    float2 o;
                    o.x = acc[ma][nn][2 * half + 0] + bb.x;
                    o.y = acc[ma][nn][2 * half + 1] + bb.y;
                    *(float2*)(C + (size_t)r * N + col) = o;
                }
            }
        }
    } else {
        const int region = n0 >> 11;   // 0=Q, 1=K, 2=V
        #pragma unroll
        for (int ma = 0; ma < 2; ma++) {
            #pragma unroll
            for (int half = 0; half < 2; half++) {
                int r  = m0 + wm * 32 + ma * 16 + gp + 8 * half;
                int bb = r >> 11;
                int s  = r & 2047;
                #pragma unroll
                for (int nn = 0; nn < 8; nn++) {
                    int col = n0 + wn * 64 + 8 * nn + 2 * cc;   // even
                    float v0 = acc[ma][nn][2 * half + 0] + bias[col];
                    float v1 = acc[ma][nn][2 * half + 1] + bias[col + 1];
                    int hd = col & 2047;
                    int h  = hd >> 7;
                    int w  = hd & 127;                          // even
                    int bh = bb * 16 + h;
                    if (region == 0) {
                        __half* dst = g_q16 + ((size_t)bh * SEQ + s) * HDIM +
                                      ((w >> 5) << 5) + perm16(w & 31);
                        *(half2*)dst = __floats2half2_rn(v0 * QSCALE, v1 * QSCALE);
                    } else if (region == 1) {
                        __half* dst = g_k16 + ((size_t)bh * SEQ + s) * HDIM +
                                      ((w >> 5) << 5) + perm16(w & 31);
                        *(half2*)dst = __floats2half2_rn(v0, v1);
                    } else {
                        size_t koff = ((size_t)(s >> 5) << 5) + perm16(s & 31);
                        g_v16[((size_t)bh * HDIM + w) * SEQ + koff] = __float2half_rn(v0);
                        g_v16[((size_t)bh * HDIM + w + 1) * SEQ + koff] = __float2half_rn(v1);
                    }
                }
            }
        }
    }
}

// ---------------------------------------------------------------------------
// Flash-attention (R12 structure), all-fp16 mma, exp2 softmax, plus
// causality-bounded work: fully-masked S blocks / PV chunks are skipped
// (warp-uniform bounds; numerics unchanged — the mask covers skipped sacc).
// ---------------------------------------------------------------------------
#define Q16_B 32768                    /* 128 rows x 4 planes x 64B */
#define K16_B 16384                    /* 64 x 4 x 64 */
#define V16_B 16384                    /* 128 x 2 x 64 */
#define ATTN_SMEM (Q16_B + 2*K16_B + 2*V16_B)   /* 98304 */

__global__ __launch_bounds__(256, 2)
void attn_mma()
{
    extern __shared__ char smc[];
    const uint32_t smb = smem_u32(smc);
    const uint32_t uQ = smb;
    const uint32_t uK = smb + Q16_B;
    const uint32_t uV = smb + Q16_B + 2 * K16_B;

    const int tid  = threadIdx.x;
    const int lane = tid & 31;
    const int wid  = tid >> 5;
    const int gp   = lane >> 2;
    const int cc   = lane & 3;
    const int qt   = (int)gridDim.x - 1 - (int)blockIdx.x;
    const int bh   = blockIdx.y;
    const size_t qbase = (size_t)bh * SEQ;

    auto fillQ = [&]() {
        #pragma unroll
        for (int t = 0; t < 8; t++) {
            int idx = tid + 256 * t;
            int r = idx >> 4, b = (idx >> 2) & 3, ch = idx & 3;
            cp16(uQ + (uint32_t)(b * 8192 + r * 64 + ((ch ^ (r & 3)) << 4)),
                 g_q16 + (qbase + qt * 128 + r) * HDIM + b * 32 + ch * 8);
        }
    };
    auto fillK = [&](int kt, int buf) {
        uint32_t base = uK + (uint32_t)(buf * K16_B);
        #pragma unroll
        for (int t = 0; t < 4; t++) {
            int idx = tid + 256 * t;
            int r = idx >> 4, b = (idx >> 2) & 3, ch = idx & 3;
            cp16(base + (uint32_t)(b * 4096 + r * 64 + ((ch ^ (r & 3)) << 4)),
                 g_k16 + (qbase + kt * 64 + r) * HDIM + b * 32 + ch * 8);
        }
    };
    auto fillV = [&](int kt, int buf) {
        uint32_t base = uV + (uint32_t)(buf * V16_B);
        #pragma unroll
        for (int t = 0; t < 4; t++) {
            int idx = tid + 256 * t;
            int d = idx >> 3, b = (idx >> 2) & 1, ch = idx & 3;
            cp16(base + (uint32_t)(b * 8192 + d * 64 + ((ch ^ (d & 3)) << 4)),
                 g_v16 + ((size_t)bh * HDIM + d) * SEQ + kt * 64 + b * 32 + ch * 8);
        }
    };

    float m[2] = {-1e30f, -1e30f}, l[2] = {0.f, 0.f};
    float oacc[16][4];
    #pragma unroll
    for (int nd = 0; nd < 16; nd++)
        #pragma unroll
        for (int q = 0; q < 4; q++) oacc[nd][q] = 0.f;

    const int nkt = 2 * qt + 2;
    fillQ(); fillK(0, 0); fillV(0, 0); CP_COMMIT();

    const int qrow = wid * 16 + gp;
    const int chA  = (cc ^ (qrow & 3)) << 4;
    const int chB  = (cc ^ (gp & 3)) << 4;
    const int qhi  = qt * 128 + wid * 16 + 15;     // warp's highest q row

    for (int kt = 0; kt < nkt; kt++) {
        const int buf = kt & 1;
        CP_WAIT0();
        __syncthreads();
        if (kt + 1 < nkt) { fillK(kt + 1, 1 - buf); fillV(kt + 1, 1 - buf); CP_COMMIT(); }

        // warp-uniform causal bounds for this tile
        const int reach = qhi - kt * 64;           // >= 79 on non-straddle tiles
        const bool act  = reach >= 0;              // any unmasked key for this warp?
        const int nmax  = act ? min(8, (reach >> 3) + 1) : 0;   // S 8-key blocks
        const int cmax  = act ? min(4, (reach >> 4) + 1) : 0;   // PV 16-key chunks

        uint32_t ah[4][4];
        if (act) {
            // ---- S = Q K^T (warp tile 16q x 64k, K=128); log2 domain ----
            float sacc[8][4];
            #pragma unroll
            for (int nn = 0; nn < 8; nn++)
                #pragma unroll
                for (int q = 0; q < 4; q++) sacc[nn][q] = 0.f;

            #pragma unroll
            for (int b = 0; b < 4; b++) {
                const char* qp = smc + b * 8192;
                const char* kp = smc + Q16_B + buf * K16_B + b * 4096;
                uint4 avA = *(const uint4*)(qp + qrow * 64 + chA);
                uint4 avB = *(const uint4*)(qp + (qrow + 8) * 64 + chA);
                #pragma unroll
                for (int nn = 0; nn < 8; nn++) {
                    if (nn < nmax) {
                        uint4 bk = *(const uint4*)(kp + (8 * nn + gp) * 64 + chB);
                        mma_f16(sacc[nn], avA.x, avB.x, avA.y, avB.y, bk.x, bk.y);
                        mma_f16(sacc[nn], avA.z, avB.z, avA.w, avB.w, bk.z, bk.w);
                    }
                }
            }

            // ---- causal mask (straddling tiles only) ----
            if (kt >= 2 * qt) {
                #pragma unroll
                for (int hq = 0; hq < 2; hq++) {
                    int qg = qt * 128 + qrow + 8 * hq;
                    #pragma unroll
                    for (int nn = 0; nn < 8; nn++) {
                        int k0 = kt * 64 + 8 * nn + 2 * cc;
                        if (k0 > qg)     sacc[nn][2 * hq]     = -1e30f;
                        if (k0 + 1 > qg) sacc[nn][2 * hq + 1] = -1e30f;
                    }
                }
            }

            // ---- online softmax (exp2 domain); pack P into PV A-fragments ----
            #pragma unroll
            for (int hq = 0; hq < 2; hq++) {
                float mx = -1e30f;
                #pragma unroll
                for (int nn = 0; nn < 8; nn++)
                    mx = fmaxf(mx, fmaxf(sacc[nn][2 * hq], sacc[nn][2 * hq + 1]));
                mx = fmaxf(mx, __shfl_xor_sync(0xffffffffu, mx, 1));
                mx = fmaxf(mx, __shfl_xor_sync(0xffffffffu, mx, 2));
                float mnew = fmaxf(m[hq], mx);
                float corr = exp2f(m[hq] - mnew);
                m[hq] = mnew;
                float rs = 0.f;
                #pragma unroll
                for (int nn = 0; nn < 8; nn++) {
                    float p0 = exp2f(sacc[nn][2 * hq]     - mnew);
                    float p1 = exp2f(sacc[nn][2 * hq + 1] - mnew);
                    rs += p0 + p1;
                    ah[nn >> 1][((nn & 1) << 1) | hq] = h2u(__floats2half2_rn(p0, p1));
                }
                rs += __shfl_xor_sync(0xffffffffu, rs, 1);
                rs += __shfl_xor_sync(0xffffffffu, rs, 2);
                l[hq] = l[hq] * corr + rs;
                #pragma unroll
                for (int nd = 0; nd < 16; nd++) {
                    oacc[nd][2 * hq]     *= corr;
                    oacc[nd][2 * hq + 1] *= corr;
                }
            }

            // ---- O += P V (skip key chunks with P == 0) ----
            #pragma unroll
            for (int pl = 0; pl < 2; pl++) {
                if (2 * pl < cmax) {
                    const char* vp = smc + Q16_B + 2 * K16_B + buf * V16_B + pl * 8192;
                    #pragma unroll
                    for (int nd = 0; nd < 16; nd++) {
                        uint4 bv = *(const uint4*)(vp + (8 * nd + gp) * 64 + chB);
                        mma_f16(oacc[nd], ah[2 * pl][0], ah[2 * pl][1],
                                ah[2 * pl][2], ah[2 * pl][3], bv.x, bv.y);
                        if (2 * pl + 1 < cmax)
                            mma_f16(oacc[nd], ah[2 * pl + 1][0], ah[2 * pl + 1][1],
                                    ah[2 * pl + 1][2], ah[2 * pl + 1][3], bv.z, bv.w);
                    }
                }
            }
        }
    }

    // ---- normalize + store (fp16 perm16 for out-proj GEMM) ----
    const int b = bh >> 4, h = bh & 15;
    #pragma unroll
    for (int hq = 0; hq < 2; hq++) {
        float inv = 1.0f / l[hq];
        size_t row = (size_t)b * SEQ + qt * 128 + wid * 16 + gp + 8 * hq;
        __half* dst = g_attnH + row * EMBED;
        #pragma unroll
        for (int nd = 0; nd < 16; nd++) {
            float o0 = oacc[nd][2 * hq]     * inv;
            float o1 = oacc[nd][2 * hq + 1] * inv;
            int j   = 8 * nd + 2 * cc;
            int blk = (h * HDIM + j) >> 5;
            *(half2*)(dst + blk * 32 + perm16(j & 31)) = __floats2half2_rn(o0, o1);
        }
    }
}

// ---------------------------------------------------------------------------
extern "C" void kernel_launch(void* const* d_in, const int* in_sizes, int n_in,
                              void* d_out, int out_size)
{
    const float* x    = (const float*)d_in[0];
    const float* Wqkv = (const float*)d_in[1];
    const float* bqkv = (const float*)d_in[2];
    const float* Wout = (const float*)d_in[3];
    const float* bout = (const float*)d_in[4];
    float* out = (float*)d_out;

    __half* attp = nullptr;
    __half* btp  = nullptr;
    __half* xpp  = nullptr;
    cudaGetSymbolAddress((void**)&attp, g_attnH);
    cudaGetSymbolAddress((void**)&btp,  g_Bt);
    cudaGetSymbolAddress((void**)&xpp,  g_xH);

    cudaFuncSetAttribute(attn_mma,
                         cudaFuncAttributeMaxDynamicSharedMemorySize, ATTN_SMEM);
    cudaFuncSetAttribute(gemm_mma,
                         cudaFuncAttributeMaxDynamicSharedMemorySize, GEMM_SMEM);

    // 1) x -> fp16 perm16
    permute_h16<<<2048, 256>>>(x, xpp, MROWS * EMBED / 4);
    // 2) W_qkv -> [N,K] fp16 perm16
    transpose_h16<<<dim3(QKVN / 32, EMBED / 32), dim3(32, 8)>>>(Wqkv, btp, EMBED, QKVN);
    // 3) QKV projection (fp16 mma), fused epilogue -> g_q16 / g_k16 / g_v16
    gemm_mma<<<dim3(QKVN / 128, MROWS / 128), 256, GEMM_SMEM>>>(
        xpp, btp, bqkv, nullptr, MROWS, QKVN, EMBED, 1);
    // 4) causal attention (fp16 mma, exp2 softmax, bounded straddle work)
    attn_mma<<<dim3(SEQ / 128, BATCH * NHEADS), 256, ATTN_SMEM>>>();
    // 5) W_out -> [N,K] fp16 perm16
    transpose_h16<<<dim3(EMBED / 32, EMBED / 32), dim3(32, 8)>>>(Wout, btp, EMBED, EMBED);
    // 6) output projection (fp16 mma)
    gemm_mma<<<dim3(EMBED / 128, MROWS / 128), 256, GEMM_SMEM>>>(
        attp, btp, bout, out, MROWS, EMBED, EMBED, 0);
}

// round 15
// speedup vs baseline: 1.0360x; 1.0276x over previous
#include <cuda_runtime.h>
#include <cuda_fp16.h>
#include <cstdint>

#define EMBED   2048
#define NHEADS  16
#define HDIM    128
#define SEQ     2048
#define BATCH   2
#define QKVN    (3*EMBED)      /* 6144 */
#define MROWS   (BATCH*SEQ)    /* 4096 */

// Scratch (static device globals — allocation-free).
__device__ __align__(16) __half g_q16[(size_t)MROWS * EMBED];   // Q fp16 perm16, scaled*log2e
__device__ __align__(16) __half g_k16[(size_t)MROWS * EMBED];   // K fp16 perm16
__device__ __align__(16) __half g_v16[(size_t)MROWS * EMBED];   // V [bh,d,2048keys] perm16
__device__ __align__(16) __half g_attnH[(size_t)MROWS * EMBED]; // attn out fp16 perm16
__device__ __align__(16) __half g_Bt[(size_t)QKVN * EMBED];     // W_qkv^T [N,K] fp16 perm16
__device__ __align__(16) __half g_BtO[(size_t)EMBED * EMBED];   // W_out^T [N,K] fp16 perm16
__device__ __align__(16) __half g_xH[(size_t)MROWS * EMBED];    // x fp16 perm16

#define ATT_SCALE 0.08838834764831845f           /* 1/sqrt(128) */
#define LOG2E     1.4426950408889634f
#define QSCALE    (ATT_SCALE * LOG2E)            /* folded: softmax in exp2 domain */

__device__ __forceinline__ void mma_f16(float* c,
                                        uint32_t a0, uint32_t a1, uint32_t a2, uint32_t a3,
                                        uint32_t b0, uint32_t b1) {
    asm volatile(
        "mma.sync.aligned.m16n8k16.row.col.f32.f16.f16.f32 "
        "{%0,%1,%2,%3}, {%4,%5,%6,%7}, {%8,%9}, {%0,%1,%2,%3};"
        : "+f"(c[0]), "+f"(c[1]), "+f"(c[2]), "+f"(c[3])
        : "r"(a0), "r"(a1), "r"(a2), "r"(a3), "r"(b0), "r"(b1));
}
__device__ __forceinline__ uint32_t h2u(half2 h) {
    return *reinterpret_cast<uint32_t*>(&h);
}
__device__ __forceinline__ uint32_t smem_u32(const void* p) {
    uint32_t a;
    asm("{ .reg .u64 t; cvta.to.shared.u64 t, %1; cvt.u32.u64 %0, t; }"
        : "=r"(a) : "l"(p));
    return a;
}
__device__ __forceinline__ void cp16(uint32_t dst, const void* src) {
    asm volatile("cp.async.ca.shared.global [%0], [%1], 16;"
                 :: "r"(dst), "l"(src) : "memory");
}
#define CP_COMMIT() asm volatile("cp.async.commit_group;" ::: "memory")
#define CP_WAIT0()  asm volatile("cp.async.wait_group 0;"  ::: "memory")
#define CP_WAIT1()  asm volatile("cp.async.wait_group 1;"  ::: "memory")

// fp16 m16n8k16 fragment permutation within a 32-half K-block:
//   slot = ((k&7)>>1)*8 + ((k>>4)&1)*4 + ((k>>3)&1)*2 + (k&1)
__device__ __forceinline__ int perm16(int k) {
    return (((k & 7) >> 1) << 3) + (((k >> 4) & 1) << 2) + (((k >> 3) & 1) << 1) + (k & 1);
}

// ---------------------------------------------------------------------------
// ONE prep kernel, three phases selected by block index range:
//   [0, 12288)        : W_qkv [2048,6144] -> g_Bt  [6144,2048] fp16 perm16
//   [12288, 16384)    : W_out [2048,2048] -> g_BtO [2048,2048] fp16 perm16
//   [16384, 18432)    : x [4096,2048] fp32 -> g_xH fp16 perm16
// ---------------------------------------------------------------------------
#define PREP_WQKV_BLKS (192 * 64)       /* (6144/32) x (2048/32) */
#define PREP_WOUT_BLKS (64 * 64)
#define PREP_PERM_BLKS 2048
#define PREP_BLKS (PREP_WQKV_BLKS + PREP_WOUT_BLKS + PREP_PERM_BLKS)

__global__ void prep_all(const float* __restrict__ x,
                         const float* __restrict__ Wqkv,
                         const float* __restrict__ Wout)
{
    const int bid = blockIdx.x;
    const int tid = threadIdx.x;

    if (bid < PREP_WQKV_BLKS + PREP_WOUT_BLKS) {
        // ---- transpose + fp16 + perm16 phase ----
        const float* W;
        __half* Wt;
        int K = EMBED, N, nbx, kby;
        if (bid < PREP_WQKV_BLKS) {
            W = Wqkv; Wt = g_Bt; N = QKVN;
            nbx = bid % 192; kby = bid / 192;
        } else {
            int i = bid - PREP_WQKV_BLKS;
            W = Wout; Wt = g_BtO; N = EMBED;
            nbx = i % 64; kby = i / 64;
        }
        __shared__ float t[32][33];
        const int kb = kby * 32, nb = nbx * 32;
        const int xx = tid & 31, yy = tid >> 5;    // (32, 8)
        #pragma unroll
        for (int i = 0; i < 32; i += 8)
            t[yy + i][xx] = W[(size_t)(kb + yy + i) * N + nb + xx];
        __syncthreads();
        #pragma unroll
        for (int i = 0; i < 32; i += 8)
            Wt[(size_t)(nb + yy + i) * K + kb + perm16(xx)] =
                __float2half_rn(t[xx][yy + i]);
    } else {
        // ---- x permute phase ----
        const int pb = bid - PREP_WQKV_BLKS - PREP_WOUT_BLKS;   // 0..2047
        const int total4 = MROWS * EMBED / 4;
        for (int idx = pb * 256 + tid; idx < total4; idx += PREP_PERM_BLKS * 256) {
            float4 v = *(const float4*)(x + 4 * (size_t)idx);
            int row = idx >> 9;
            int c4  = idx & 511;
            int w   = 4 * (c4 & 7);
            __half* dst = g_xH + (size_t)row * EMBED + ((c4 >> 3) << 5);
            *(half2*)(dst + perm16(w))     = __floats2half2_rn(v.x, v.y);
            *(half2*)(dst + perm16(w + 2)) = __floats2half2_rn(v.z, v.w);
        }
    }
}

// ---------------------------------------------------------------------------
// FP16 mma.sync (m16n8k16) GEMM, cp.async 3-stage pipeline, 2 CTAs/SM.
// (unchanged — at the mma.sync issue ceiling)
// ---------------------------------------------------------------------------
#define STAGE_B 16384
#define NSTAGE 3
#define GEMM_SMEM (NSTAGE * STAGE_B)     /* 49152 -> 2 CTAs/SM */

__global__ __launch_bounds__(256, 2)
void gemm_mma(const __half* __restrict__ Ap, const __half* __restrict__ Bp,
              const float* __restrict__ bias, float* __restrict__ C,
              int M, int N, int K, int mode)
{
    extern __shared__ char smc[];
    const uint32_t smb = smem_u32(smc);

    const int tid  = threadIdx.x;
    const int lane = tid & 31;
    const int wid  = tid >> 5;
    const int wm   = wid & 3;
    const int wn   = wid >> 2;
    const int m0   = blockIdx.y * 128;
    const int n0   = blockIdx.x * 128;
    const int gp   = lane >> 2;
    const int cc   = lane & 3;

    auto fill = [&](int s, int st) {
        const int k0 = s << 5;
        uint32_t dA = smb + (uint32_t)(st * STAGE_B);
        uint32_t dB = dA + 8192;
        const __half* As = Ap + (size_t)m0 * K + k0;
        const __half* Bs = Bp + (size_t)n0 * K + k0;
        #pragma unroll
        for (int t = 0; t < 2; t++) {
            int idx = tid + 256 * t;
            int row = idx >> 2, ch = idx & 3;
            uint32_t off = (uint32_t)(row * 64 + ((ch ^ (row & 3)) << 4));
            cp16(dA + off, As + (size_t)row * K + ch * 8);
            cp16(dB + off, Bs + (size_t)row * K + ch * 8);
        }
    };

    float acc[2][8][4];
    #pragma unroll
    for (int ma = 0; ma < 2; ma++)
        #pragma unroll
        for (int nn = 0; nn < 8; nn++)
            #pragma unroll
            for (int q = 0; q < 4; q++) acc[ma][nn][q] = 0.f;

    fill(0, 0); CP_COMMIT();
    fill(1, 1); CP_COMMIT();

    const int chsw = cc ^ (gp & 3);
    const int NST = K >> 5;
    int st = 0;
    for (int s = 0; s < NST; s++) {
        CP_WAIT1();
        __syncthreads();

        const char* a = smc + st * STAGE_B;
        const char* b = a + 8192;

        uint4 av[4];
        #pragma unroll
        for (int r = 0; r < 4; r++) {
            int row = wm * 32 + gp + 8 * r;
            av[r] = *(const uint4*)(a + row * 64 + (chsw << 4));
        }
        #pragma unroll
        for (int nh = 0; nh < 2; nh++) {
            uint4 bv[4];
            #pragma unroll
            for (int j = 0; j < 4; j++) {
                int row = wn * 64 + 8 * (4 * nh + j) + gp;
                bv[j] = *(const uint4*)(b + row * 64 + (chsw << 4));
            }
            #pragma unroll
            for (int ma = 0; ma < 2; ma++) {
                #pragma unroll
                for (int j = 0; j < 4; j++)
                    mma_f16(acc[ma][4 * nh + j], av[2 * ma].x, av[2 * ma + 1].x,
                            av[2 * ma].y, av[2 * ma + 1].y, bv[j].x, bv[j].y);
                #pragma unroll
                for (int j = 0; j < 4; j++)
                    mma_f16(acc[ma][4 * nh + j], av[2 * ma].z, av[2 * ma + 1].z,
                            av[2 * ma].w, av[2 * ma + 1].w, bv[j].z, bv[j].w);
            }
        }
        if (s + 2 < NST) {
            int nb = st + 2; if (nb >= 3) nb -= 3;
            fill(s + 2, nb);
        }
        CP_COMMIT();
        if (++st == 3) st = 0;
    }

    if (mode == 0) {
        #pragma unroll
        for (int ma = 0; ma < 2; ma++) {
            int rbase = m0 + wm * 32 + ma * 16 + gp;
            #pragma unroll
            for (int half = 0; half < 2; half++) {
                int r = rbase + 8 * half;
                #pragma unroll
                for (int nn = 0; nn < 8; nn++) {
                    int col = n0 + wn * 64 + 8 * nn + 2 * cc;
                    float2 bb = *(const float2*)(bias + col);
                    float2 o;
                    o.x = acc[ma][nn][2 * half + 0] + bb.x;
                    o.y = acc[ma][nn][2 * half + 1] + bb.y;
                    *(float2*)(C + (size_t)r * N + col) = o;
                }
            }
        }
    } else {
        const int region = n0 >> 11;   // 0=Q, 1=K, 2=V
        #pragma unroll
        for (int ma = 0; ma < 2; ma++) {
            #pragma unroll
            for (int half = 0; half < 2; half++) {
                int r  = m0 + wm * 32 + ma * 16 + gp + 8 * half;
                int bb = r >> 11;
                int s  = r & 2047;
                #pragma unroll
                for (int nn = 0; nn < 8; nn++) {
                    int col = n0 + wn * 64 + 8 * nn + 2 * cc;   // even
                    float v0 = acc[ma][nn][2 * half + 0] + bias[col];
                    float v1 = acc[ma][nn][2 * half + 1] + bias[col + 1];
                    int hd = col & 2047;
                    int h  = hd >> 7;
                    int w  = hd & 127;                          // even
                    int bh = bb * 16 + h;
                    if (region == 0) {
                        __half* dst = g_q16 + ((size_t)bh * SEQ + s) * HDIM +
                                      ((w >> 5) << 5) + perm16(w & 31);
                        *(half2*)dst = __floats2half2_rn(v0 * QSCALE, v1 * QSCALE);
                    } else if (region == 1) {
                        __half* dst = g_k16 + ((size_t)bh * SEQ + s) * HDIM +
                                      ((w >> 5) << 5) + perm16(w & 31);
                        *(half2*)dst = __floats2half2_rn(v0, v1);
                    } else {
                        size_t koff = ((size_t)(s >> 5) << 5) + perm16(s & 31);
                        g_v16[((size_t)bh * HDIM + w) * SEQ + koff] = __float2half_rn(v0);
                        g_v16[((size_t)bh * HDIM + w + 1) * SEQ + koff] = __float2half_rn(v1);
                    }
                }
            }
        }
    }
}

// ---------------------------------------------------------------------------
// Flash-attention — EXACT Round-12 version (proven 212 us local optimum):
// all-fp16 mma, exp2 softmax, P never touches smem, K/V double-buffered,
// one barrier per tile, 2 CTAs/SM.
// ---------------------------------------------------------------------------
#define Q16_B 32768                    /* 128 rows x 4 planes x 64B */
#define K16_B 16384                    /* 64 x 4 x 64 */
#define V16_B 16384                    /* 128 x 2 x 64 */
#define ATTN_SMEM (Q16_B + 2*K16_B + 2*V16_B)   /* 98304 */

__global__ __launch_bounds__(256, 2)
void attn_mma()
{
    extern __shared__ char smc[];
    const uint32_t smb = smem_u32(smc);
    const uint32_t uQ = smb;
    const uint32_t uK = smb + Q16_B;
    const uint32_t uV = smb + Q16_B + 2 * K16_B;

    const int tid  = threadIdx.x;
    const int lane = tid & 31;
    const int wid  = tid >> 5;
    const int gp   = lane >> 2;
    const int cc   = lane & 3;
    const int qt   = (int)gridDim.x - 1 - (int)blockIdx.x;
    const int bh   = blockIdx.y;
    const size_t qbase = (size_t)bh * SEQ;

    auto fillQ = [&]() {
        #pragma unroll
        for (int t = 0; t < 8; t++) {
            int idx = tid + 256 * t;
            int r = idx >> 4, b = (idx >> 2) & 3, ch = idx & 3;
            cp16(uQ + (uint32_t)(b * 8192 + r * 64 + ((ch ^ (r & 3)) << 4)),
                 g_q16 + (qbase + qt * 128 + r) * HDIM + b * 32 + ch * 8);
        }
    };
    auto fillK = [&](int kt, int buf) {
        uint32_t base = uK + (uint32_t)(buf * K16_B);
        #pragma unroll
        for (int t = 0; t < 4; t++) {
            int idx = tid + 256 * t;
            int r = idx >> 4, b = (idx >> 2) & 3, ch = idx & 3;
            cp16(base + (uint32_t)(b * 4096 + r * 64 + ((ch ^ (r & 3)) << 4)),
                 g_k16 + (qbase + kt * 64 + r) * HDIM + b * 32 + ch * 8);
        }
    };
    auto fillV = [&](int kt, int buf) {
        uint32_t base = uV + (uint32_t)(buf * V16_B);
        #pragma unroll
        for (int t = 0; t < 4; t++) {
            int idx = tid + 256 * t;
            int d = idx >> 3, b = (idx >> 2) & 1, ch = idx & 3;
            cp16(base + (uint32_t)(b * 8192 + d * 64 + ((ch ^ (d & 3)) << 4)),
                 g_v16 + ((size_t)bh * HDIM + d) * SEQ + kt * 64 + b * 32 + ch * 8);
        }
    };

    float m[2] = {-1e30f, -1e30f}, l[2] = {0.f, 0.f};
    float oacc[16][4];
    #pragma unroll
    for (int nd = 0; nd < 16; nd++)
        #pragma unroll
        for (int q = 0; q < 4; q++) oacc[nd][q] = 0.f;

    const int nkt = 2 * qt + 2;
    fillQ(); fillK(0, 0); fillV(0, 0); CP_COMMIT();

    const int qrow = wid * 16 + gp;
    const int chA  = (cc ^ (qrow & 3)) << 4;
    const int chB  = (cc ^ (gp & 3)) << 4;

    for (int kt = 0; kt < nkt; kt++) {
        const int buf = kt & 1;
        CP_WAIT0();
        __syncthreads();
        if (kt + 1 < nkt) { fillK(kt + 1, 1 - buf); fillV(kt + 1, 1 - buf); CP_COMMIT(); }

        // ---- S = Q K^T (warp tile 16q x 64k, K=128); S is log2-domain ----
        float sacc[8][4];
        #pragma unroll
        for (int nn = 0; nn < 8; nn++)
            #pragma unroll
            for (int q = 0; q < 4; q++) sacc[nn][q] = 0.f;

        #pragma unroll
        for (int b = 0; b < 4; b++) {
            const char* qp = smc + b * 8192;
            const char* kp = smc + Q16_B + buf * K16_B + b * 4096;
            uint4 avA = *(const uint4*)(qp + qrow * 64 + chA);
            uint4 avB = *(const uint4*)(qp + (qrow + 8) * 64 + chA);
            #pragma unroll
            for (int nn = 0; nn < 8; nn++) {
                uint4 bk = *(const uint4*)(kp + (8 * nn + gp) * 64 + chB);
                mma_f16(sacc[nn], avA.x, avB.x, avA.y, avB.y, bk.x, bk.y);
                mma_f16(sacc[nn], avA.z, avB.z, avA.w, avB.w, bk.z, bk.w);
            }
        }

        // ---- causal mask (straddling tiles only) ----
        if (kt >= 2 * qt) {
            #pragma unroll
            for (int hq = 0; hq < 2; hq++) {
                int qg = qt * 128 + qrow + 8 * hq;
                #pragma unroll
                for (int nn = 0; nn < 8; nn++) {
                    int k0 = kt * 64 + 8 * nn + 2 * cc;
                    if (k0 > qg)     sacc[nn][2 * hq]     = -1e30f;
                    if (k0 + 1 > qg) sacc[nn][2 * hq + 1] = -1e30f;
                }
            }
        }

        // ---- online softmax (exp2 domain); pack P into PV A-fragments ----
        uint32_t ah[4][4];
        #pragma unroll
        for (int hq = 0; hq < 2; hq++) {
            float mx = -1e30f;
            #pragma unroll
            for (int nn = 0; nn < 8; nn++)
                mx = fmaxf(mx, fmaxf(sacc[nn][2 * hq], sacc[nn][2 * hq + 1]));
            mx = fmaxf(mx, __shfl_xor_sync(0xffffffffu, mx, 1));
            mx = fmaxf(mx, __shfl_xor_sync(0xffffffffu, mx, 2));
            float mnew = fmaxf(m[hq], mx);
            float corr = exp2f(m[hq] - mnew);
            m[hq] = mnew;
            float rs = 0.f;
            #pragma unroll
            for (int nn = 0; nn < 8; nn++) {
                float p0 = exp2f(sacc[nn][2 * hq]     - mnew);
                float p1 = exp2f(sacc[nn][2 * hq + 1] - mnew);
                rs += p0 + p1;
                ah[nn >> 1][((nn & 1) << 1) | hq] = h2u(__floats2half2_rn(p0, p1));
            }
            rs += __shfl_xor_sync(0xffffffffu, rs, 1);
            rs += __shfl_xor_sync(0xffffffffu, rs, 2);
            l[hq] = l[hq] * corr + rs;
            #pragma unroll
            for (int nd = 0; nd < 16; nd++) {
                oacc[nd][2 * hq]     *= corr;
                oacc[nd][2 * hq + 1] *= corr;
            }
        }

        // ---- O += P V ----
        #pragma unroll
        for (int pl = 0; pl < 2; pl++) {
            const char* vp = smc + Q16_B + 2 * K16_B + buf * V16_B + pl * 8192;
            #pragma unroll
            for (int nd = 0; nd < 16; nd++) {
                uint4 bv = *(const uint4*)(vp + (8 * nd + gp) * 64 + chB);
                mma_f16(oacc[nd], ah[2 * pl][0], ah[2 * pl][1],
                        ah[2 * pl][2], ah[2 * pl][3], bv.x, bv.y);
                mma_f16(oacc[nd], ah[2 * pl + 1][0], ah[2 * pl + 1][1],
                        ah[2 * pl + 1][2], ah[2 * pl + 1][3], bv.z, bv.w);
            }
        }
    }

    // ---- normalize + store (fp16 perm16 for out-proj GEMM) ----
    const int b = bh >> 4, h = bh & 15;
    #pragma unroll
    for (int hq = 0; hq < 2; hq++) {
        float inv = 1.0f / l[hq];
        size_t row = (size_t)b * SEQ + qt * 128 + wid * 16 + gp + 8 * hq;
        __half* dst = g_attnH + row * EMBED;
        #pragma unroll
        for (int nd = 0; nd < 16; nd++) {
            float o0 = oacc[nd][2 * hq]     * inv;
            float o1 = oacc[nd][2 * hq + 1] * inv;
            int j   = 8 * nd + 2 * cc;
            int blk = (h * HDIM + j) >> 5;
            *(half2*)(dst + blk * 32 + perm16(j & 31)) = __floats2half2_rn(o0, o1);
        }
    }
}

// ---------------------------------------------------------------------------
extern "C" void kernel_launch(void* const* d_in, const int* in_sizes, int n_in,
                              void* d_out, int out_size)
{
    const float* x    = (const float*)d_in[0];
    const float* Wqkv = (const float*)d_in[1];
    const float* bqkv = (const float*)d_in[2];
    const float* Wout = (const float*)d_in[3];
    const float* bout = (const float*)d_in[4];
    float* out = (float*)d_out;

    __half* attp = nullptr;
    __half* btp  = nullptr;
    __half* btop = nullptr;
    __half* xpp  = nullptr;
    cudaGetSymbolAddress((void**)&attp, g_attnH);
    cudaGetSymbolAddress((void**)&btp,  g_Bt);
    cudaGetSymbolAddress((void**)&btop, g_BtO);
    cudaGetSymbolAddress((void**)&xpp,  g_xH);

    cudaFuncSetAttribute(attn_mma,
                         cudaFuncAttributeMaxDynamicSharedMemorySize, ATTN_SMEM);
    cudaFuncSetAttribute(gemm_mma,
                         cudaFuncAttributeMaxDynamicSharedMemorySize, GEMM_SMEM);

    // 1) single prep pass: both weight transposes + x permute (fp16 perm16)
    prep_all<<<PREP_BLKS, 256>>>(x, Wqkv, Wout);
    // 2) QKV projection (fp16 mma), fused epilogue -> g_q16 / g_k16 / g_v16
    gemm_mma<<<dim3(QKVN / 128, MROWS / 128), 256, GEMM_SMEM>>>(
        xpp, btp, bqkv, nullptr, MROWS, QKVN, EMBED, 1);
    // 3) causal attention (R12 fp16 mma, exp2 softmax, 2 CTAs/SM)
    attn_mma<<<dim3(SEQ / 128, BATCH * NHEADS), 256, ATTN_SMEM>>>();
    // 4) output projection (fp16 mma)
    gemm_mma<<<dim3(EMBED / 128, MROWS / 128), 256, GEMM_SMEM>>>(
        attp, btop, bout, out, MROWS, EMBED, EMBED, 0);
}